// round 7
// baseline (speedup 1.0000x reference)
#include <cuda_runtime.h>
#include <cstdint>

#define BB 32
#define NN 512
#define HH 128
constexpr float LN_EPS = 1e-5f;

// h transposed AND pre-converted to tf32 bits: g_hT[b][d][j]  (B, H, N), 8 MB
__device__ uint32_t g_hT[(size_t)BB * HH * NN];

// ---------------------------------------------------------------------------
// helpers
// ---------------------------------------------------------------------------
__device__ __forceinline__ uint32_t f2tf32(float x) {
    uint32_t r;
    asm("cvt.rna.tf32.f32 %0, %1;" : "=r"(r) : "f"(x));
    return r;
}

__device__ __forceinline__ uint32_t smem_u32(const void* p) {
    uint32_t a;
    asm("{ .reg .u64 t; cvta.to.shared.u64 t, %1; cvt.u32.u64 %0, t; }"
        : "=r"(a) : "l"(p));
    return a;
}

__device__ __forceinline__ void mma_sync_tf32(float* d, const uint32_t* a, const uint32_t* b) {
    asm volatile(
        "mma.sync.aligned.m16n8k8.row.col.f32.tf32.tf32.f32 "
        "{%0,%1,%2,%3}, {%4,%5,%6,%7}, {%8,%9}, {%0,%1,%2,%3};\n"
        : "+f"(d[0]), "+f"(d[1]), "+f"(d[2]), "+f"(d[3])
        : "r"(a[0]), "r"(a[1]), "r"(a[2]), "r"(a[3]), "r"(b[0]), "r"(b[1]));
}

__device__ __forceinline__ void ldm4(uint32_t* r, uint32_t saddr) {
    asm volatile(
        "ldmatrix.sync.aligned.m8n8.x4.shared.b16 {%0,%1,%2,%3}, [%4];"
        : "=r"(r[0]), "=r"(r[1]), "=r"(r[2]), "=r"(r[3])
        : "r"(saddr));
}

__device__ __forceinline__ void cp16(uint32_t dst, const void* src) {
    asm volatile("cp.async.cg.shared.global [%0], [%1], 16;"
                 :: "r"(dst), "l"(src) : "memory");
}
__device__ __forceinline__ void cp_commit() {
    asm volatile("cp.async.commit_group;" ::: "memory");
}
template<int N> __device__ __forceinline__ void cp_wait() {
    asm volatile("cp.async.wait_group %0;" :: "n"(N) : "memory");
}

// ---------------------------------------------------------------------------
// Stage 1: h = silu(layernorm(s @ W1^T + b1)), stored TRANSPOSED + tf32 bits
// ---------------------------------------------------------------------------
__global__ __launch_bounds__(256) void lin1_ln_silu_kernel(
    const float* __restrict__ s, const float* __restrict__ W1,
    const float* __restrict__ b1)
{
    __shared__ float smem[64 * 133];
    float* As = smem;                 // [64][36]
    float* Bs = smem + 64 * 36;       // [128][36]
    float* Hs = smem;                 // [64][133]

    const int tid  = threadIdx.x;
    const int r0   = blockIdx.x * 64;
    const int w    = tid >> 5;
    const int lane = tid & 31;
    const int g    = lane >> 2;
    const int tg   = lane & 3;
    const int wm   = w & 1;
    const int wn   = w >> 1;

    float acc[2][4][4];
    #pragma unroll
    for (int i = 0; i < 2; i++)
        #pragma unroll
        for (int j = 0; j < 4; j++)
            #pragma unroll
            for (int k = 0; k < 4; k++) acc[i][j][k] = 0.f;

    const uint32_t* A32 = (const uint32_t*)As;
    const uint32_t* B32 = (const uint32_t*)Bs;

    for (int kc = 0; kc < 4; kc++) {
        const int k0 = kc * 32;
        __syncthreads();
        #pragma unroll
        for (int it = 0; it < 2; it++) {
            int idx = tid + it * 256;
            int row = idx >> 3, q = idx & 7;
            float4 v = *(const float4*)(s + (size_t)(r0 + row) * HH + k0 + q * 4);
            uint32_t* dst = (uint32_t*)(As + row * 36 + q * 4);
            dst[0] = f2tf32(v.x); dst[1] = f2tf32(v.y);
            dst[2] = f2tf32(v.z); dst[3] = f2tf32(v.w);
        }
        #pragma unroll
        for (int it = 0; it < 4; it++) {
            int idx = tid + it * 256;
            int n = idx >> 3, q = idx & 7;
            float4 v = *(const float4*)(W1 + (size_t)n * HH + k0 + q * 4);
            uint32_t* dst = (uint32_t*)(Bs + n * 36 + q * 4);
            dst[0] = f2tf32(v.x); dst[1] = f2tf32(v.y);
            dst[2] = f2tf32(v.z); dst[3] = f2tf32(v.w);
        }
        __syncthreads();
        #pragma unroll
        for (int ks = 0; ks < 4; ks++) {
            const int kk = ks * 8;
            uint32_t af[2][4], bf[4][2];
            #pragma unroll
            for (int mt = 0; mt < 2; mt++) {
                int rm = wm * 32 + mt * 16;
                af[mt][0] = A32[(rm + g) * 36 + kk + tg];
                af[mt][1] = A32[(rm + g + 8) * 36 + kk + tg];
                af[mt][2] = A32[(rm + g) * 36 + kk + tg + 4];
                af[mt][3] = A32[(rm + g + 8) * 36 + kk + tg + 4];
            }
            #pragma unroll
            for (int nt = 0; nt < 4; nt++) {
                int cn = wn * 32 + nt * 8 + g;
                bf[nt][0] = B32[cn * 36 + kk + tg];
                bf[nt][1] = B32[cn * 36 + kk + tg + 4];
            }
            #pragma unroll
            for (int mt = 0; mt < 2; mt++)
                #pragma unroll
                for (int nt = 0; nt < 4; nt++)
                    mma_sync_tf32(acc[mt][nt], af[mt], bf[nt]);
        }
    }

    __syncthreads();
    #pragma unroll
    for (int mt = 0; mt < 2; mt++) {
        #pragma unroll
        for (int nt = 0; nt < 4; nt++) {
            int rm = wm * 32 + mt * 16 + g;
            int cn = wn * 32 + nt * 8 + 2 * tg;
            Hs[rm * 133 + cn]           = acc[mt][nt][0];
            Hs[rm * 133 + cn + 1]       = acc[mt][nt][1];
            Hs[(rm + 8) * 133 + cn]     = acc[mt][nt][2];
            Hs[(rm + 8) * 133 + cn + 1] = acc[mt][nt][3];
        }
    }
    __syncthreads();

    #pragma unroll
    for (int rr = 0; rr < 8; rr++) {
        int row = w * 8 + rr;
        float x[4];
        float sum = 0.f, sq = 0.f;
        #pragma unroll
        for (int k = 0; k < 4; k++) {
            float v = Hs[row * 133 + lane + 32 * k] + __ldg(b1 + lane + 32 * k);
            x[k] = v; sum += v; sq += v * v;
        }
        #pragma unroll
        for (int o = 16; o > 0; o >>= 1) {
            sum += __shfl_xor_sync(0xffffffffu, sum, o);
            sq  += __shfl_xor_sync(0xffffffffu, sq, o);
        }
        float mu  = sum * (1.f / 128.f);
        float var = sq * (1.f / 128.f) - mu * mu;
        float inv = rsqrtf(var + LN_EPS);
        #pragma unroll
        for (int k = 0; k < 4; k++) {
            float yv = (x[k] - mu) * inv;
            Hs[row * 133 + lane + 32 * k] = yv / (1.f + __expf(-yv));
        }
    }
    __syncthreads();

    // Transposed write-out as tf32 bits: g_hT[b][d][n]
    const int b  = r0 >> 9;
    const int n0 = r0 & 511;
    #pragma unroll
    for (int it = 0; it < 8; it++) {
        int idx = tid + it * 256;
        int d = idx >> 4;
        int q = idx & 15;
        uint4 v;
        v.x = f2tf32(Hs[(q * 4 + 0) * 133 + d]);
        v.y = f2tf32(Hs[(q * 4 + 1) * 133 + d]);
        v.z = f2tf32(Hs[(q * 4 + 2) * 133 + d]);
        v.w = f2tf32(Hs[(q * 4 + 3) * 133 + d]);
        *(uint4*)(g_hT + ((size_t)b * HH + d) * NN + n0 + q * 4) = v;
    }
}

// ---------------------------------------------------------------------------
// Stage 2: mma.sync tf32 GEMM, sized for 2 CTAs/SM.
// Block: batch b, m-tile 64 (m=i*3+c), N=128 (d), K=512 (j) in 16 chunks of 32.
// 256 threads = 8 warps (2m x 4n), warp tile 32m x 32n.
// Smem (75KB): A[2][64][36] | B ring[3] swizzled | mask ring[3]. ev via regs.
// ---------------------------------------------------------------------------
#define AST 36
#define OFF_A0 0u
#define OFF_A1 9216u
#define OFF_B  18432u      /* + r*16384 */
#define OFF_MK 67584u      /* + r*3072  */
#define SMEM2  76800

__global__ __launch_bounds__(256, 2)
void cfconv5_kernel(const float* __restrict__ ev,
                    const float* __restrict__ mask,
                    float* __restrict__ out)
{
    extern __shared__ __align__(16) char smemc[];
    const uint32_t sb = smem_u32(smemc);

    const int tid  = threadIdx.x;
    const int w    = tid >> 5;
    const int lane = tid & 31;
    const int g    = lane >> 2;
    const int tg   = lane & 3;
    const int wm   = w & 1;       // 2 warp rows (32 m each)
    const int wn   = w >> 1;      // 4 warp cols (32 n each)

    const int b    = blockIdx.y;
    const int m0   = blockIdx.x * 64;
    const int i_lo = m0 / 3;
    const int i_hi = (m0 + 63) / 3;
    const int icnt = i_hi - i_lo + 1;     // <= 23

    const float*    evB   = ev   + (((size_t)b * NN) * NN) * 3;
    const float*    maskB = mask + ((size_t)b * NN) * NN;
    const uint32_t* hTB   = g_hT + ((size_t)b * HH) * NN;

    // ldmatrix per-lane constants (mappings verbatim from verified kernels)
    const int arow  = (lane & 7) + ((lane >> 3) & 1) * 8;
    const int ahalf = (lane >> 4) & 1;
    const uint32_t aoff = (uint32_t)(((wm * 32 + arow) * AST + ahalf * 4) * 4);
    const int brow  = (lane & 7) + ((lane >> 4) & 1) * 8;
    const int bhalf = (lane >> 3) & 1;

    float acc[2][4][4];
    #pragma unroll
    for (int mt = 0; mt < 2; mt++)
        #pragma unroll
        for (int nt = 0; nt < 4; nt++)
            #pragma unroll
            for (int k = 0; k < 4; k++) acc[mt][nt][k] = 0.f;

    // per-thread ev staging decomposition (row = 24 float4 of 96 floats)
    int erow[3], eq[3];
    #pragma unroll
    for (int it = 0; it < 3; it++) {
        int idx = tid + it * 256;
        erow[it] = idx / 24;
        eq[it]   = idx - erow[it] * 24;
    }
    const int ev_n = icnt * 24;

    // ---- cp.async: B (h_T) + mask for chunk ch ----
    auto issue = [&](int ch) {
        const int r  = ch % 3;
        const int j0 = ch * 32;
        const uint32_t bb = sb + OFF_B + (uint32_t)r * 16384u;
        #pragma unroll
        for (int it = 0; it < 4; it++) {
            int idx = tid + it * 256;
            int d = idx >> 3, q = idx & 7;
            cp16(bb + (uint32_t)(d * 128 + ((q ^ (d & 7)) << 4)),
                 hTB + (size_t)d * NN + j0 + q * 4);
        }
        const uint32_t mb = sb + OFF_MK + (uint32_t)r * 3072u;
        {
            int idx = tid;
            if (idx < icnt * 8) {
                cp16(mb + (uint32_t)idx * 16u,
                     maskB + (size_t)(i_lo + (idx >> 3)) * NN + j0 + (idx & 7) * 4);
            }
        }
        cp_commit();
    };

    // ---- stage ev for chunk ch into registers ----
    float4 evr[3];
    auto stage_ev = [&](int ch) {
        const int j0 = ch * 32;
        #pragma unroll
        for (int it = 0; it < 3; it++) {
            int idx = tid + it * 256;
            if (idx < ev_n)
                evr[it] = *(const float4*)(evB +
                    ((size_t)(i_lo + erow[it]) * NN + j0) * 3 + eq[it] * 4);
        }
    };

    // ---- scatter staged ev * mask -> A[p], mask from ring slot of chunk ch ----
    auto scatterA = [&](int p, int ch) {
        const int r = ch % 3;
        const float* mkr = (const float*)(smemc + OFF_MK + (size_t)r * 3072u);
        uint32_t* Ab = (uint32_t*)(smemc + (p ? OFF_A1 : OFF_A0));
        #pragma unroll
        for (int it = 0; it < 3; it++) {
            int idx = tid + it * 256;
            if (idx < ev_n) {
                int rr = erow[it], q = eq[it];
                int jc0 = q * 4, ja = jc0 / 3;
                float mA = mkr[rr * 32 + ja];
                float mB2 = mkr[rr * 32 + ja + 1];
                int mbase = (i_lo + rr) * 3 - m0;
                float fv[4] = {evr[it].x, evr[it].y, evr[it].z, evr[it].w};
                #pragma unroll
                for (int e = 0; e < 4; e++) {
                    int jc = jc0 + e;
                    int jl = jc / 3, c = jc - 3 * jl;
                    int m = mbase + c;
                    if (m >= 0 && m < 64)
                        Ab[m * AST + jl] = f2tf32(fv[e] * (jl == ja ? mA : mB2));
                }
            }
        }
    };

    // Prologue: 3 chunks of B/mask in flight; build A0.
    issue(0); issue(1); issue(2);
    cp_wait<2>();
    __syncthreads();
    stage_ev(0);
    scatterA(0, 0);
    __syncthreads();

    for (int ch = 0; ch < 16; ch++) {
        const int p = ch & 1;
        const uint32_t Ab = sb + (p ? OFF_A1 : OFF_A0);
        const uint32_t Bb = sb + OFF_B + (uint32_t)(ch % 3) * 16384u;

        // Hoisted LDG for next chunk's ev — latency hides under the MMA block.
        if (ch < 15) stage_ev(ch + 1);

        // MMA: 4 k-steps of 8
        #pragma unroll
        for (int ks = 0; ks < 4; ks++) {
            uint32_t af[2][4], bf[2][4];
            #pragma unroll
            for (int mt = 0; mt < 2; mt++)
                ldm4(af[mt], Ab + aoff + (uint32_t)(mt * 16 * AST * 4 + ks * 32));
            #pragma unroll
            for (int bt = 0; bt < 2; bt++) {
                int n = wn * 32 + bt * 16 + brow;
                int jq = ks * 2 + bhalf;
                ldm4(bf[bt], Bb + (uint32_t)(n * 128 + ((jq ^ (n & 7)) << 4)));
            }
            #pragma unroll
            for (int mt = 0; mt < 2; mt++)
                #pragma unroll
                for (int nt = 0; nt < 4; nt++)
                    mma_sync_tf32(acc[mt][nt], af[mt], &bf[nt >> 1][(nt & 1) * 2]);
        }

        if (ch < 14)       cp_wait<1>();
        else if (ch == 14) cp_wait<0>();
        __syncthreads();

        if (ch < 15) {
            scatterA(p ^ 1, ch + 1);
            if (ch < 13) issue(ch + 3);
        }
        __syncthreads();
    }

    // Epilogue
    const size_t obase = ((size_t)b * 1536 + m0) * HH;
    #pragma unroll
    for (int mt = 0; mt < 2; mt++) {
        #pragma unroll
        for (int nt = 0; nt < 4; nt++) {
            int m  = wm * 32 + mt * 16 + g;
            int cn = wn * 32 + nt * 8 + 2 * tg;
            *(float2*)(out + obase + (size_t)m * HH + cn) =
                make_float2(acc[mt][nt][0], acc[mt][nt][1]);
            *(float2*)(out + obase + (size_t)(m + 8) * HH + cn) =
                make_float2(acc[mt][nt][2], acc[mt][nt][3]);
        }
    }
}

// ---------------------------------------------------------------------------
// Launch
// ---------------------------------------------------------------------------
extern "C" void kernel_launch(void* const* d_in, const int* in_sizes, int n_in,
                              void* d_out, int out_size) {
    (void)in_sizes; (void)n_in; (void)out_size;
    const float* s    = (const float*)d_in[0];
    const float* ev   = (const float*)d_in[1];
    const float* mask = (const float*)d_in[2];
    const float* W1   = (const float*)d_in[3];
    const float* b1   = (const float*)d_in[4];
    float* out = (float*)d_out;

    cudaFuncSetAttribute(cfconv5_kernel,
                         cudaFuncAttributeMaxDynamicSharedMemorySize, SMEM2);

    lin1_ln_silu_kernel<<<256, 256>>>(s, W1, b1);
    cfconv5_kernel<<<dim3(24, 32), 256, SMEM2>>>(ev, mask, out);
}

// round 11
// speedup vs baseline: 1.9579x; 1.9579x over previous
#include <cuda_runtime.h>
#include <cstdint>

#define BB 32
#define NN 512
#define HH 128
constexpr float LN_EPS = 1e-5f;

// h transposed AND pre-converted to tf32 bits: g_hT[b][d][j]  (B, H, N), 8 MB
__device__ uint32_t g_hT[(size_t)BB * HH * NN];

// ---------------------------------------------------------------------------
// helpers
// ---------------------------------------------------------------------------
__device__ __forceinline__ uint32_t f2tf32(float x) {
    uint32_t r;
    asm("cvt.rna.tf32.f32 %0, %1;" : "=r"(r) : "f"(x));
    return r;
}

__device__ __forceinline__ uint32_t smem_u32(const void* p) {
    uint32_t a;
    asm("{ .reg .u64 t; cvta.to.shared.u64 t, %1; cvt.u32.u64 %0, t; }"
        : "=r"(a) : "l"(p));
    return a;
}

__device__ __forceinline__ void mma_sync_tf32(float* d, const uint32_t* a, const uint32_t* b) {
    asm volatile(
        "mma.sync.aligned.m16n8k8.row.col.f32.tf32.tf32.f32 "
        "{%0,%1,%2,%3}, {%4,%5,%6,%7}, {%8,%9}, {%0,%1,%2,%3};\n"
        : "+f"(d[0]), "+f"(d[1]), "+f"(d[2]), "+f"(d[3])
        : "r"(a[0]), "r"(a[1]), "r"(a[2]), "r"(a[3]), "r"(b[0]), "r"(b[1]));
}

__device__ __forceinline__ void ldm4(uint32_t* r, uint32_t saddr) {
    asm volatile(
        "ldmatrix.sync.aligned.m8n8.x4.shared.b16 {%0,%1,%2,%3}, [%4];"
        : "=r"(r[0]), "=r"(r[1]), "=r"(r[2]), "=r"(r[3])
        : "r"(saddr));
}

__device__ __forceinline__ void cp16(uint32_t dst, const void* src) {
    asm volatile("cp.async.cg.shared.global [%0], [%1], 16;"
                 :: "r"(dst), "l"(src) : "memory");
}
__device__ __forceinline__ void cp_commit() {
    asm volatile("cp.async.commit_group;" ::: "memory");
}
template<int N> __device__ __forceinline__ void cp_wait() {
    asm volatile("cp.async.wait_group %0;" :: "n"(N) : "memory");
}

// ---------------------------------------------------------------------------
// Stage 1: h = silu(layernorm(s @ W1^T + b1)), stored TRANSPOSED + tf32 bits
// ---------------------------------------------------------------------------
__global__ __launch_bounds__(256) void lin1_ln_silu_kernel(
    const float* __restrict__ s, const float* __restrict__ W1,
    const float* __restrict__ b1)
{
    __shared__ float smem[64 * 133];
    float* As = smem;                 // [64][36]
    float* Bs = smem + 64 * 36;       // [128][36]
    float* Hs = smem;                 // [64][133]

    const int tid  = threadIdx.x;
    const int r0   = blockIdx.x * 64;
    const int w    = tid >> 5;
    const int lane = tid & 31;
    const int g    = lane >> 2;
    const int tg   = lane & 3;
    const int wm   = w & 1;
    const int wn   = w >> 1;

    float acc[2][4][4];
    #pragma unroll
    for (int i = 0; i < 2; i++)
        #pragma unroll
        for (int j = 0; j < 4; j++)
            #pragma unroll
            for (int k = 0; k < 4; k++) acc[i][j][k] = 0.f;

    const uint32_t* A32 = (const uint32_t*)As;
    const uint32_t* B32 = (const uint32_t*)Bs;

    for (int kc = 0; kc < 4; kc++) {
        const int k0 = kc * 32;
        __syncthreads();
        #pragma unroll
        for (int it = 0; it < 2; it++) {
            int idx = tid + it * 256;
            int row = idx >> 3, q = idx & 7;
            float4 v = *(const float4*)(s + (size_t)(r0 + row) * HH + k0 + q * 4);
            uint32_t* dst = (uint32_t*)(As + row * 36 + q * 4);
            dst[0] = f2tf32(v.x); dst[1] = f2tf32(v.y);
            dst[2] = f2tf32(v.z); dst[3] = f2tf32(v.w);
        }
        #pragma unroll
        for (int it = 0; it < 4; it++) {
            int idx = tid + it * 256;
            int n = idx >> 3, q = idx & 7;
            float4 v = *(const float4*)(W1 + (size_t)n * HH + k0 + q * 4);
            uint32_t* dst = (uint32_t*)(Bs + n * 36 + q * 4);
            dst[0] = f2tf32(v.x); dst[1] = f2tf32(v.y);
            dst[2] = f2tf32(v.z); dst[3] = f2tf32(v.w);
        }
        __syncthreads();
        #pragma unroll
        for (int ks = 0; ks < 4; ks++) {
            const int kk = ks * 8;
            uint32_t af[2][4], bf[4][2];
            #pragma unroll
            for (int mt = 0; mt < 2; mt++) {
                int rm = wm * 32 + mt * 16;
                af[mt][0] = A32[(rm + g) * 36 + kk + tg];
                af[mt][1] = A32[(rm + g + 8) * 36 + kk + tg];
                af[mt][2] = A32[(rm + g) * 36 + kk + tg + 4];
                af[mt][3] = A32[(rm + g + 8) * 36 + kk + tg + 4];
            }
            #pragma unroll
            for (int nt = 0; nt < 4; nt++) {
                int cn = wn * 32 + nt * 8 + g;
                bf[nt][0] = B32[cn * 36 + kk + tg];
                bf[nt][1] = B32[cn * 36 + kk + tg + 4];
            }
            #pragma unroll
            for (int mt = 0; mt < 2; mt++)
                #pragma unroll
                for (int nt = 0; nt < 4; nt++)
                    mma_sync_tf32(acc[mt][nt], af[mt], bf[nt]);
        }
    }

    __syncthreads();
    #pragma unroll
    for (int mt = 0; mt < 2; mt++) {
        #pragma unroll
        for (int nt = 0; nt < 4; nt++) {
            int rm = wm * 32 + mt * 16 + g;
            int cn = wn * 32 + nt * 8 + 2 * tg;
            Hs[rm * 133 + cn]           = acc[mt][nt][0];
            Hs[rm * 133 + cn + 1]       = acc[mt][nt][1];
            Hs[(rm + 8) * 133 + cn]     = acc[mt][nt][2];
            Hs[(rm + 8) * 133 + cn + 1] = acc[mt][nt][3];
        }
    }
    __syncthreads();

    #pragma unroll
    for (int rr = 0; rr < 8; rr++) {
        int row = w * 8 + rr;
        float x[4];
        float sum = 0.f, sq = 0.f;
        #pragma unroll
        for (int k = 0; k < 4; k++) {
            float v = Hs[row * 133 + lane + 32 * k] + __ldg(b1 + lane + 32 * k);
            x[k] = v; sum += v; sq += v * v;
        }
        #pragma unroll
        for (int o = 16; o > 0; o >>= 1) {
            sum += __shfl_xor_sync(0xffffffffu, sum, o);
            sq  += __shfl_xor_sync(0xffffffffu, sq, o);
        }
        float mu  = sum * (1.f / 128.f);
        float var = sq * (1.f / 128.f) - mu * mu;
        float inv = rsqrtf(var + LN_EPS);
        #pragma unroll
        for (int k = 0; k < 4; k++) {
            float yv = (x[k] - mu) * inv;
            Hs[row * 133 + lane + 32 * k] = yv / (1.f + __expf(-yv));
        }
    }
    __syncthreads();

    // Transposed write-out as tf32 bits: g_hT[b][d][n]
    const int b  = r0 >> 9;
    const int n0 = r0 & 511;
    #pragma unroll
    for (int it = 0; it < 8; it++) {
        int idx = tid + it * 256;
        int d = idx >> 4;
        int q = idx & 15;
        uint4 v;
        v.x = f2tf32(Hs[(q * 4 + 0) * 133 + d]);
        v.y = f2tf32(Hs[(q * 4 + 1) * 133 + d]);
        v.z = f2tf32(Hs[(q * 4 + 2) * 133 + d]);
        v.w = f2tf32(Hs[(q * 4 + 3) * 133 + d]);
        *(uint4*)(g_hT + ((size_t)b * HH + d) * NN + n0 + q * 4) = v;
    }
}

// ---------------------------------------------------------------------------
// Stage 2: mma.sync tf32 GEMM, m-tile 192 (= exactly 64 i-rows, no clipping).
// Block: batch b, m in [bx*192, bx*192+192), N=128 (d), K=512 (j) in 16 chunks
// of 32. 512 threads = 16 warps (4m x 4n), warp tile 48m x 32n (mt=3).
// A[2][192][36] double-buffered; B ring[3] swizzled via cp.async.
// ev+mask staged in registers one chunk ahead (vectorized: 1 thread = 1 i-row
// x 4-j group = 3 ev float4 + 1 mask float4 -> 3 STS.128).
// Plain __syncthreads only (verified R4/R5 schedule).
// ---------------------------------------------------------------------------
#define AST 36
#define A_TILE_B (192 * AST * 4)          /* 27648 */
#define OFF_A0 0u
#define OFF_A1 27648u
#define OFF_B  55296u                      /* + r*16384, r<3 */
#define SMEM2  104448

__global__ __launch_bounds__(512, 1)
void cfconv7_kernel(const float* __restrict__ ev,
                    const float* __restrict__ mask,
                    float* __restrict__ out)
{
    extern __shared__ __align__(16) char smemc[];
    const uint32_t sb = smem_u32(smemc);

    const int tid  = threadIdx.x;
    const int w    = tid >> 5;
    const int lane = tid & 31;
    const int g    = lane >> 2;
    const int tg   = lane & 3;
    const int wm   = w & 3;       // 4 warp rows (48 m each)
    const int wn   = w >> 2;      // 4 warp cols (32 n each)

    const int b    = blockIdx.y;
    const int i_lo = blockIdx.x * 64;     // 64 i-rows -> m-tile of 192 exactly

    const float*    evB   = ev   + (((size_t)b * NN) * NN) * 3;
    const float*    maskB = mask + ((size_t)b * NN) * NN;
    const uint32_t* hTB   = g_hT + ((size_t)b * HH) * NN;

    // ldmatrix per-lane constants (mappings verbatim from verified kernels)
    const int arow  = (lane & 7) + ((lane >> 3) & 1) * 8;
    const int ahalf = (lane >> 4) & 1;
    const uint32_t aoff = (uint32_t)(((wm * 48 + arow) * AST + ahalf * 4) * 4);
    const int brow  = (lane & 7) + ((lane >> 4) & 1) * 8;
    const int bhalf = (lane >> 3) & 1;

    float acc[3][4][4];
    #pragma unroll
    for (int mt = 0; mt < 3; mt++)
        #pragma unroll
        for (int nt = 0; nt < 4; nt++)
            #pragma unroll
            for (int k = 0; k < 4; k++) acc[mt][nt][k] = 0.f;

    // scatter ownership: one thread = (i-row rr, 4-j group jg)
    const int rr = tid >> 3;              // 0..63
    const int jg = tid & 7;               // 0..7 (j = jg*4 .. jg*4+3)
    const float* ev_base = evB + ((size_t)(i_lo + rr) * NN) * 3 + (size_t)jg * 12;
    const float* mk_base = maskB + (size_t)(i_lo + rr) * NN + jg * 4;

    // ---- cp.async: B (h_T swizzled) for chunk ch into ring slot ch%3 ----
    auto issue = [&](int ch) {
        const int r  = ch % 3;
        const int j0 = ch * 32;
        const uint32_t bb = sb + OFF_B + (uint32_t)r * 16384u;
        #pragma unroll
        for (int it = 0; it < 2; it++) {
            int idx = tid + it * 512;
            int d = idx >> 3, q = idx & 7;
            cp16(bb + (uint32_t)(d * 128 + ((q ^ (d & 7)) << 4)),
                 hTB + (size_t)d * NN + j0 + q * 4);
        }
        cp_commit();
    };

    // ---- stage ev + mask for chunk ch into registers (plain LDG) ----
    float4 e0, e1, e2, mk;
    auto stage = [&](int ch) {
        const float* ep = ev_base + (size_t)ch * 96;   // (j0)*3 floats
        e0 = *(const float4*)(ep);
        e1 = *(const float4*)(ep + 4);
        e2 = *(const float4*)(ep + 8);
        mk = *(const float4*)(mk_base + ch * 32);
    };

    // ---- scatter staged regs -> A[p]: rows m=rr*3+c, cols jg*4..+3 ----
    auto scatterA = [&](int p) {
        uint32_t* Ab = (uint32_t*)(smemc + (p ? OFF_A1 : OFF_A0));
        float ef[12] = {e0.x, e0.y, e0.z, e0.w,
                        e1.x, e1.y, e1.z, e1.w,
                        e2.x, e2.y, e2.z, e2.w};
        float mkf[4] = {mk.x, mk.y, mk.z, mk.w};
        #pragma unroll
        for (int c = 0; c < 3; c++) {
            uint4 v;
            v.x = f2tf32(ef[0 + c] * mkf[0]);
            v.y = f2tf32(ef[3 + c] * mkf[1]);
            v.z = f2tf32(ef[6 + c] * mkf[2]);
            v.w = f2tf32(ef[9 + c] * mkf[3]);
            *(uint4*)(Ab + (rr * 3 + c) * AST + jg * 4) = v;
        }
    };

    // Prologue: 3 B chunks in flight; stage+scatter chunk 0.
    issue(0); issue(1); issue(2);
    stage(0);
    scatterA(0);
    cp_wait<2>();
    __syncthreads();

    for (int ch = 0; ch < 16; ch++) {
        const int p = ch & 1;
        const uint32_t Ab = sb + (p ? OFF_A1 : OFF_A0);
        const uint32_t Bb = sb + OFF_B + (uint32_t)(ch % 3) * 16384u;

        // LDG for next chunk's ev+mask — latency hides under the MMA block.
        if (ch < 15) stage(ch + 1);

        // MMA: 4 k-steps of 8
        #pragma unroll
        for (int ks = 0; ks < 4; ks++) {
            uint32_t af[3][4], bf[2][4];
            #pragma unroll
            for (int mt = 0; mt < 3; mt++)
                ldm4(af[mt], Ab + aoff + (uint32_t)(mt * 16 * AST * 4 + ks * 32));
            #pragma unroll
            for (int bt = 0; bt < 2; bt++) {
                int n = wn * 32 + bt * 16 + brow;
                int jq = ks * 2 + bhalf;
                ldm4(bf[bt], Bb + (uint32_t)(n * 128 + ((jq ^ (n & 7)) << 4)));
            }
            #pragma unroll
            for (int mt = 0; mt < 3; mt++)
                #pragma unroll
                for (int nt = 0; nt < 4; nt++)
                    mma_sync_tf32(acc[mt][nt], af[mt], &bf[nt >> 1][(nt & 1) * 2]);
        }

        if (ch < 14)       cp_wait<1>();
        else if (ch == 14) cp_wait<0>();
        __syncthreads();

        if (ch < 15) {
            scatterA(p ^ 1);
            if (ch < 13) issue(ch + 3);
        }
        __syncthreads();
    }

    // Epilogue: out[(b*1536 + bx*192 + m)*128 + d]
    const size_t obase = ((size_t)b * 1536 + (size_t)blockIdx.x * 192) * HH;
    #pragma unroll
    for (int mt = 0; mt < 3; mt++) {
        #pragma unroll
        for (int nt = 0; nt < 4; nt++) {
            int m  = wm * 48 + mt * 16 + g;
            int cn = wn * 32 + nt * 8 + 2 * tg;
            *(float2*)(out + obase + (size_t)m * HH + cn) =
                make_float2(acc[mt][nt][0], acc[mt][nt][1]);
            *(float2*)(out + obase + (size_t)(m + 8) * HH + cn) =
                make_float2(acc[mt][nt][2], acc[mt][nt][3]);
        }
    }
}

// ---------------------------------------------------------------------------
// Launch
// ---------------------------------------------------------------------------
extern "C" void kernel_launch(void* const* d_in, const int* in_sizes, int n_in,
                              void* d_out, int out_size) {
    (void)in_sizes; (void)n_in; (void)out_size;
    const float* s    = (const float*)d_in[0];
    const float* ev   = (const float*)d_in[1];
    const float* mask = (const float*)d_in[2];
    const float* W1   = (const float*)d_in[3];
    const float* b1   = (const float*)d_in[4];
    float* out = (float*)d_out;

    cudaFuncSetAttribute(cfconv7_kernel,
                         cudaFuncAttributeMaxDynamicSharedMemorySize, SMEM2);

    lin1_ln_silu_kernel<<<256, 256>>>(s, W1, b1);
    cfconv7_kernel<<<dim3(8, 32), 512, SMEM2>>>(ev, mask, out);
}

// round 12
// speedup vs baseline: 2.0796x; 1.0622x over previous
#include <cuda_runtime.h>
#include <cstdint>

#define BB 32
#define NN 512
#define HH 128
constexpr float LN_EPS = 1e-5f;

// h transposed AND pre-converted to tf32 bits: g_hT[b][d][j]  (B, H, N), 8 MB
__device__ uint32_t g_hT[(size_t)BB * HH * NN];

// ---------------------------------------------------------------------------
// helpers
// ---------------------------------------------------------------------------
__device__ __forceinline__ uint32_t f2tf32(float x) {
    uint32_t r;
    asm("cvt.rna.tf32.f32 %0, %1;" : "=r"(r) : "f"(x));
    return r;
}

__device__ __forceinline__ uint32_t smem_u32(const void* p) {
    uint32_t a;
    asm("{ .reg .u64 t; cvta.to.shared.u64 t, %1; cvt.u32.u64 %0, t; }"
        : "=r"(a) : "l"(p));
    return a;
}

__device__ __forceinline__ void mma_sync_tf32(float* d, const uint32_t* a, const uint32_t* b) {
    asm volatile(
        "mma.sync.aligned.m16n8k8.row.col.f32.tf32.tf32.f32 "
        "{%0,%1,%2,%3}, {%4,%5,%6,%7}, {%8,%9}, {%0,%1,%2,%3};\n"
        : "+f"(d[0]), "+f"(d[1]), "+f"(d[2]), "+f"(d[3])
        : "r"(a[0]), "r"(a[1]), "r"(a[2]), "r"(a[3]), "r"(b[0]), "r"(b[1]));
}

__device__ __forceinline__ void ldm4(uint32_t* r, uint32_t saddr) {
    asm volatile(
        "ldmatrix.sync.aligned.m8n8.x4.shared.b16 {%0,%1,%2,%3}, [%4];"
        : "=r"(r[0]), "=r"(r[1]), "=r"(r[2]), "=r"(r[3])
        : "r"(saddr));
}

__device__ __forceinline__ void cp16(uint32_t dst, const void* src) {
    asm volatile("cp.async.cg.shared.global [%0], [%1], 16;"
                 :: "r"(dst), "l"(src) : "memory");
}
__device__ __forceinline__ void cp_commit() {
    asm volatile("cp.async.commit_group;" ::: "memory");
}
template<int N> __device__ __forceinline__ void cp_wait() {
    asm volatile("cp.async.wait_group %0;" :: "n"(N) : "memory");
}

// ---------------------------------------------------------------------------
// Stage 1 (v2): h = silu(layernorm(s @ W1^T + b1)), TRANSPOSED + tf32 bits.
// 128 rows/CTA, 512 threads (16 warps, 4x4), single K=128 pass, 4 barriers.
// ---------------------------------------------------------------------------
#define AST1 132
#define HST1 133
#define LN1_SMEM 135168    /* max(2*128*132, 128*133) * 4 */

__global__ __launch_bounds__(512, 1)
void lin1b_kernel(const float* __restrict__ s, const float* __restrict__ W1,
                  const float* __restrict__ b1)
{
    extern __shared__ __align__(16) float sm1[];
    float* As = sm1;                   // [128][132] tf32 bits of s rows
    float* Ws = sm1 + 128 * AST1;      // [128][132] tf32 bits of W1 rows
    float* Hs = sm1;                   // [128][133] (aliases As after MMA)

    const int tid  = threadIdx.x;
    const int r0   = blockIdx.x * 128;
    const int w    = tid >> 5;
    const int lane = tid & 31;
    const int g    = lane >> 2;
    const int tg   = lane & 3;
    const int wm   = w & 3;            // 4 warp rows (32 rows each)
    const int wn   = w >> 2;           // 4 warp cols (32 cols each)

    // Load s tile (128 x 128) and W1 (128 x 128) as tf32 bits
    #pragma unroll
    for (int it = 0; it < 8; it++) {
        int idx = tid + it * 512;
        int row = idx >> 5, q = idx & 31;
        float4 v = *(const float4*)(s + (size_t)(r0 + row) * HH + q * 4);
        uint32_t* dst = (uint32_t*)(As + row * AST1 + q * 4);
        dst[0] = f2tf32(v.x); dst[1] = f2tf32(v.y);
        dst[2] = f2tf32(v.z); dst[3] = f2tf32(v.w);
    }
    #pragma unroll
    for (int it = 0; it < 8; it++) {
        int idx = tid + it * 512;
        int n = idx >> 5, q = idx & 31;
        float4 v = *(const float4*)(W1 + (size_t)n * HH + q * 4);
        uint32_t* dst = (uint32_t*)(Ws + n * AST1 + q * 4);
        dst[0] = f2tf32(v.x); dst[1] = f2tf32(v.y);
        dst[2] = f2tf32(v.z); dst[3] = f2tf32(v.w);
    }
    __syncthreads();

    float acc[2][4][4];
    #pragma unroll
    for (int i = 0; i < 2; i++)
        #pragma unroll
        for (int j = 0; j < 4; j++)
            #pragma unroll
            for (int k = 0; k < 4; k++) acc[i][j][k] = 0.f;

    const uint32_t* A32 = (const uint32_t*)As;
    const uint32_t* B32 = (const uint32_t*)Ws;

    #pragma unroll
    for (int ks = 0; ks < 16; ks++) {
        const int kk = ks * 8;
        uint32_t af[2][4], bf[4][2];
        #pragma unroll
        for (int mt = 0; mt < 2; mt++) {
            int rm = wm * 32 + mt * 16;
            af[mt][0] = A32[(rm + g) * AST1 + kk + tg];
            af[mt][1] = A32[(rm + g + 8) * AST1 + kk + tg];
            af[mt][2] = A32[(rm + g) * AST1 + kk + tg + 4];
            af[mt][3] = A32[(rm + g + 8) * AST1 + kk + tg + 4];
        }
        #pragma unroll
        for (int nt = 0; nt < 4; nt++) {
            int cn = wn * 32 + nt * 8 + g;
            bf[nt][0] = B32[cn * AST1 + kk + tg];
            bf[nt][1] = B32[cn * AST1 + kk + tg + 4];
        }
        #pragma unroll
        for (int mt = 0; mt < 2; mt++)
            #pragma unroll
            for (int nt = 0; nt < 4; nt++)
                mma_sync_tf32(acc[mt][nt], af[mt], bf[nt]);
    }
    __syncthreads();

    // Accumulators -> Hs[128][133]
    #pragma unroll
    for (int mt = 0; mt < 2; mt++) {
        #pragma unroll
        for (int nt = 0; nt < 4; nt++) {
            int rm = wm * 32 + mt * 16 + g;
            int cn = wn * 32 + nt * 8 + 2 * tg;
            Hs[rm * HST1 + cn]           = acc[mt][nt][0];
            Hs[rm * HST1 + cn + 1]       = acc[mt][nt][1];
            Hs[(rm + 8) * HST1 + cn]     = acc[mt][nt][2];
            Hs[(rm + 8) * HST1 + cn + 1] = acc[mt][nt][3];
        }
    }
    __syncthreads();

    // LayerNorm + SiLU (8 rows per warp), write back into Hs
    #pragma unroll
    for (int rr = 0; rr < 8; rr++) {
        int row = w * 8 + rr;
        float x[4];
        float sum = 0.f, sq = 0.f;
        #pragma unroll
        for (int k = 0; k < 4; k++) {
            float v = Hs[row * HST1 + lane + 32 * k] + __ldg(b1 + lane + 32 * k);
            x[k] = v; sum += v; sq += v * v;
        }
        #pragma unroll
        for (int o = 16; o > 0; o >>= 1) {
            sum += __shfl_xor_sync(0xffffffffu, sum, o);
            sq  += __shfl_xor_sync(0xffffffffu, sq, o);
        }
        float mu  = sum * (1.f / 128.f);
        float var = sq * (1.f / 128.f) - mu * mu;
        float inv = rsqrtf(var + LN_EPS);
        #pragma unroll
        for (int k = 0; k < 4; k++) {
            float yv = (x[k] - mu) * inv;
            Hs[row * HST1 + lane + 32 * k] = yv / (1.f + __expf(-yv));
        }
    }
    __syncthreads();

    // Transposed write-out as tf32 bits: g_hT[b][d][n], 128 j's per block
    const int b  = r0 >> 9;
    const int n0 = r0 & 511;
    #pragma unroll
    for (int it = 0; it < 8; it++) {
        int idx = tid + it * 512;       // 0..4095
        int d = idx >> 5;               // 0..127
        int q = idx & 31;               // float4 index along 128 j's
        uint4 v;
        v.x = f2tf32(Hs[(q * 4 + 0) * HST1 + d]);
        v.y = f2tf32(Hs[(q * 4 + 1) * HST1 + d]);
        v.z = f2tf32(Hs[(q * 4 + 2) * HST1 + d]);
        v.w = f2tf32(Hs[(q * 4 + 3) * HST1 + d]);
        *(uint4*)(g_hT + ((size_t)b * HH + d) * NN + n0 + q * 4) = v;
    }
}

// ---------------------------------------------------------------------------
// Stage 2: mma.sync tf32 GEMM, m-tile 192 (= exactly 64 i-rows).
// 4-slot B ring -> ONE __syncthreads per chunk.
// Block: batch b, m in [bx*192, +192), N=128, K=512 in 16 chunks of 32.
// 512 threads = 16 warps (4m x 4n), warp tile 48m x 32n.
// ---------------------------------------------------------------------------
#define AST 36
#define OFF_A0 0u
#define OFF_A1 27648u
#define OFF_B  55296u                   /* + r*16384, r<4 */
#define SMEM2  120832

__global__ __launch_bounds__(512, 1)
void cfconv8_kernel(const float* __restrict__ ev,
                    const float* __restrict__ mask,
                    float* __restrict__ out)
{
    extern __shared__ __align__(16) char smemc[];
    const uint32_t sb = smem_u32(smemc);

    const int tid  = threadIdx.x;
    const int w    = tid >> 5;
    const int lane = tid & 31;
    const int g    = lane >> 2;
    const int tg   = lane & 3;
    const int wm   = w & 3;       // 4 warp rows (48 m each)
    const int wn   = w >> 2;      // 4 warp cols (32 n each)

    const int b    = blockIdx.y;
    const int i_lo = blockIdx.x * 64;     // 64 i-rows -> m-tile 192 exactly

    const float*    evB   = ev   + (((size_t)b * NN) * NN) * 3;
    const float*    maskB = mask + ((size_t)b * NN) * NN;
    const uint32_t* hTB   = g_hT + ((size_t)b * HH) * NN;

    // ldmatrix per-lane constants (verified mappings)
    const int arow  = (lane & 7) + ((lane >> 3) & 1) * 8;
    const int ahalf = (lane >> 4) & 1;
    const uint32_t aoff = (uint32_t)(((wm * 48 + arow) * AST + ahalf * 4) * 4);
    const int brow  = (lane & 7) + ((lane >> 4) & 1) * 8;
    const int bhalf = (lane >> 3) & 1;

    float acc[3][4][4];
    #pragma unroll
    for (int mt = 0; mt < 3; mt++)
        #pragma unroll
        for (int nt = 0; nt < 4; nt++)
            #pragma unroll
            for (int k = 0; k < 4; k++) acc[mt][nt][k] = 0.f;

    // scatter ownership: one thread = (i-row rr, 4-j group jg)
    const int rr = tid >> 3;              // 0..63
    const int jg = tid & 7;               // 0..7
    const float* ev_base = evB + ((size_t)(i_lo + rr) * NN) * 3 + (size_t)jg * 12;
    const float* mk_base = maskB + (size_t)(i_lo + rr) * NN + jg * 4;

    // ---- cp.async: B (h_T swizzled) for chunk ch into ring slot ch&3 ----
    auto issue = [&](int ch) {
        const int r  = ch & 3;
        const int j0 = ch * 32;
        const uint32_t bb = sb + OFF_B + (uint32_t)r * 16384u;
        #pragma unroll
        for (int it = 0; it < 2; it++) {
            int idx = tid + it * 512;
            int d = idx >> 3, q = idx & 7;
            cp16(bb + (uint32_t)(d * 128 + ((q ^ (d & 7)) << 4)),
                 hTB + (size_t)d * NN + j0 + q * 4);
        }
        cp_commit();
    };

    // ---- stage ev + mask for chunk ch into registers ----
    float4 e0, e1, e2, mk;
    auto stage = [&](int ch) {
        const float* ep = ev_base + (size_t)ch * 96;
        e0 = *(const float4*)(ep);
        e1 = *(const float4*)(ep + 4);
        e2 = *(const float4*)(ep + 8);
        mk = *(const float4*)(mk_base + ch * 32);
    };

    // ---- scatter staged regs -> A[p]: rows m=rr*3+c, cols jg*4..+3 ----
    auto scatterA = [&](int p) {
        uint32_t* Ab = (uint32_t*)(smemc + (p ? OFF_A1 : OFF_A0));
        float ef[12] = {e0.x, e0.y, e0.z, e0.w,
                        e1.x, e1.y, e1.z, e1.w,
                        e2.x, e2.y, e2.z, e2.w};
        float mkf[4] = {mk.x, mk.y, mk.z, mk.w};
        #pragma unroll
        for (int c = 0; c < 3; c++) {
            uint4 v;
            v.x = f2tf32(ef[0 + c] * mkf[0]);
            v.y = f2tf32(ef[3 + c] * mkf[1]);
            v.z = f2tf32(ef[6 + c] * mkf[2]);
            v.w = f2tf32(ef[9 + c] * mkf[3]);
            *(uint4*)(Ab + (rr * 3 + c) * AST + jg * 4) = v;
        }
    };

    // Prologue: 3 B chunks in flight; stage+scatter chunk 0; B[0] resident.
    issue(0); issue(1); issue(2);
    stage(0);
    scatterA(0);
    cp_wait<2>();
    __syncthreads();

    for (int ch = 0; ch < 16; ch++) {
        const int p = ch & 1;
        const uint32_t Ab = sb + (p ? OFF_A1 : OFF_A0);
        const uint32_t Bb = sb + OFF_B + (uint32_t)(ch & 3) * 16384u;

        // LDG for next chunk's ev+mask — latency hides under the MMA block.
        if (ch < 15) stage(ch + 1);

        // MMA: 4 k-steps of 8
        #pragma unroll
        for (int ks = 0; ks < 4; ks++) {
            uint32_t af[3][4], bf[2][4];
            #pragma unroll
            for (int mt = 0; mt < 3; mt++)
                ldm4(af[mt], Ab + aoff + (uint32_t)(mt * 16 * AST * 4 + ks * 32));
            #pragma unroll
            for (int bt = 0; bt < 2; bt++) {
                int n = wn * 32 + bt * 16 + brow;
                int jq = ks * 2 + bhalf;
                ldm4(bf[bt], Bb + (uint32_t)(n * 128 + ((jq ^ (n & 7)) << 4)));
            }
            #pragma unroll
            for (int mt = 0; mt < 3; mt++)
                #pragma unroll
                for (int nt = 0; nt < 4; nt++)
                    mma_sync_tf32(acc[mt][nt], af[mt], &bf[nt >> 1][(nt & 1) * 2]);
        }

        // A[p^1] free since MMA(ch-1) (fenced by prev sync) -> scatter now.
        if (ch < 15) scatterA(p ^ 1);
        // B slot (ch+3)&3 == (ch-1)&3: readers done at MMA(ch-1), fenced.
        if (ch < 13) issue(ch + 3);

        // B[ch+1] completion before the sync publishes it to all threads.
        if (ch <= 12)      cp_wait<2>();
        else if (ch == 13) cp_wait<1>();
        else if (ch == 14) cp_wait<0>();
        __syncthreads();
    }

    // Epilogue: out[(b*1536 + bx*192 + m)*128 + d]
    const size_t obase = ((size_t)b * 1536 + (size_t)blockIdx.x * 192) * HH;
    #pragma unroll
    for (int mt = 0; mt < 3; mt++) {
        #pragma unroll
        for (int nt = 0; nt < 4; nt++) {
            int m  = wm * 48 + mt * 16 + g;
            int cn = wn * 32 + nt * 8 + 2 * tg;
            *(float2*)(out + obase + (size_t)m * HH + cn) =
                make_float2(acc[mt][nt][0], acc[mt][nt][1]);
            *(float2*)(out + obase + (size_t)(m + 8) * HH + cn) =
                make_float2(acc[mt][nt][2], acc[mt][nt][3]);
        }
    }
}

// ---------------------------------------------------------------------------
// Launch
// ---------------------------------------------------------------------------
extern "C" void kernel_launch(void* const* d_in, const int* in_sizes, int n_in,
                              void* d_out, int out_size) {
    (void)in_sizes; (void)n_in; (void)out_size;
    const float* s    = (const float*)d_in[0];
    const float* ev   = (const float*)d_in[1];
    const float* mask = (const float*)d_in[2];
    const float* W1   = (const float*)d_in[3];
    const float* b1   = (const float*)d_in[4];
    float* out = (float*)d_out;

    cudaFuncSetAttribute(lin1b_kernel,
                         cudaFuncAttributeMaxDynamicSharedMemorySize, LN1_SMEM);
    cudaFuncSetAttribute(cfconv8_kernel,
                         cudaFuncAttributeMaxDynamicSharedMemorySize, SMEM2);

    lin1b_kernel<<<128, 512, LN1_SMEM>>>(s, W1, b1);
    cfconv8_kernel<<<dim3(8, 32), 512, SMEM2>>>(ev, mask, out);
}